// round 7
// baseline (speedup 1.0000x reference)
#include <cuda_runtime.h>
#include <math_constants.h>

// ProgressReward — round 6: single kernel, grid-cooperative boundary table.
//
// Grid = B*nsplit blocks (128 here -> single wave, 1 block/SM). Phases:
//  P0  boundary detect: block covers a 1/grid segment of sorted poly_batch;
//      threads write g_bound[v] = lower_bound(poly_batch, v) at value
//      discontinuities. Independent of qb -> starts immediately, overlapping
//      the agent_ptr->agent_batch chain and query-point loads.
//  P1  grid spin barrier (g_sync1); then lo=g_bound[qb], hi=g_bound[qb+1]
//      (two L2-hot loads) replace the per-block count pass of round 5.
//  P2  stage slice s of [lo,hi): pack (c,s,a,bv) float4 in smem; off-route
//      (int32 mask via L2) folds in as a=+INF.
//  P3  scan: 16 groups x 32 lanes; lane t = timestep, both ego+expert per
//      thread; track (best,index); winner x/x_pre recomputed per chunk.
//  P4  combine: block partials -> device scratch; last sibling block (per
//      g_done[b]) reduces NSPLIT partials in ascending-s order (first-min
//      preserved), writes out[b], resets g_done[b]. g_sync1/2 self-reset by
//      the globally-last block -> graph replays see identical state.

#define NUM_HIST 4
#define INTERVAL 5
#define IP_ROWS  36
#define L_ROWS   180
#define TPB      512
#define GROUPS   16
#define NSPLIT   4
#define CHUNK    512
#define B_MAX    256

__device__ float g_pd[B_MAX * NSPLIT * 64];
__device__ float g_pp[B_MAX * NSPLIT * 64];
__device__ int   g_done[B_MAX];          // zero-init; self-resetting
__device__ int   g_bound[B_MAX + 2];
__device__ int   g_sync1, g_sync2;       // zero-init; self-resetting

__global__ void __launch_bounds__(TPB)
progress_reward_kernel(
    const int*   __restrict__ poly_batch,
    const float* __restrict__ poly_pos,        // (P,2)
    const float* __restrict__ poly_heading,    // (P,)
    const int*   __restrict__ edge_index,      // (2,P)
    const int*   __restrict__ on_route_mask,   // (NG,) int32 bool
    const int*   __restrict__ agent_ptr,       // (B+1,)
    const float* __restrict__ infer_pos,       // (A,36,2)
    const int*   __restrict__ agent_batch,     // (A,)
    const float* __restrict__ agent_pos,       // (A,180,2)
    float*       __restrict__ out,             // (B,)
    int P, int Bc, int nsplit)
{
    __shared__ float4 s4[CHUNK];                   // 8 KB
    __shared__ float  redD[2][GROUPS][32];         // 4 KB
    __shared__ float  redP[2][GROUPS][32];         // 4 KB
    __shared__ int    s_fin;
    __shared__ float  s_sum[2];

    const int grid = gridDim.x;
    const int b    = blockIdx.x / nsplit;
    const int s    = blockIdx.x - b * nsplit;
    const int tid  = threadIdx.x;
    const int g    = tid >> 5;
    const int t    = tid & 31;

    if (tid == 0) s_fin = 0;

    // ---- P0: boundary detection over my segment (indices 0..P inclusive) --
    {
        const int seg = (P + grid) / grid;                 // covers P+1 slots
        const int i0  = blockIdx.x * seg;
        const int i1  = min(i0 + seg, P + 1);
        for (int i = i0 + tid; i < i1; i += TPB) {
            const int v  = (i < P) ? poly_batch[i]     : Bc;
            const int vp = (i > 0) ? poly_batch[i - 1] : -1;
            for (int w = vp + 1; w <= v; w++)
                if (w >= 0 && w <= Bc) g_bound[w] = i;
        }
    }

    // ---- query points + qb (independent loads, overlap P0) ----
    const int aidx = agent_ptr[b];
    const float2* ip = (const float2*)(infer_pos + (size_t)aidx * (IP_ROWS * 2));
    const float2 qe  = ip[NUM_HIST     + t];
    const float2 qep = ip[NUM_HIST - 1 + t];
    const float2* ap = (const float2*)(agent_pos + (size_t)aidx * (L_ROWS * 2));
    const float2 qc  = ap[(4 + t) * INTERVAL];
    const float2 qcp = ap[(3 + t) * INTERVAL];
    int qb = agent_batch[aidx];
    if (qb < 0) qb = 0;
    if (qb > Bc - 1) qb = Bc - 1;

    // ---- P1: grid barrier, then read my batch's range ----
    if (tid == 0) {
        __threadfence();                                   // publish g_bound
        atomicAdd(&g_sync1, 1);
        while (*(volatile int*)&g_sync1 < grid) { }
    }
    __syncthreads();
    __threadfence();                                       // acquire g_bound

    const int lo  = g_bound[qb];
    const int hi  = g_bound[qb + 1];
    const int len = hi - lo;
    const int Ls  = lo + (int)(((long long)len * s)       / nsplit);
    const int Le  = lo + (int)(((long long)len * (s + 1)) / nsplit);

    const float2* pp2 = (const float2*)poly_pos;

    float beE = CUDART_INF_F, beX = CUDART_INF_F;
    int   biE = -1,           biX = -1;
    float bxE = 0.f, bpE = 0.f, bxX = 0.f, bpX = 0.f;

    for (int base = Ls; base < Le; base += CHUNK) {
        const int cnt = min(CHUNK, Le - base);

        // P2: stage (c, s, a=c*px+s*py | +INF off-route, bv=c*py-s*px)
        for (int i = tid; i < cnt; i += TPB) {
            const int p = base + i;
            const float2 pos = pp2[p];
            const float h  = poly_heading[p];
            const float ch = cosf(h);
            const float sh = sinf(h);
            const int poly = edge_index[P + p];
            const int on   = on_route_mask[poly];
            float4 v;
            v.x = ch;
            v.y = sh;
            v.z = on ? fmaf(ch, pos.x, sh * pos.y) : CUDART_INF_F;
            v.w = fmaf(ch, pos.y, -sh * pos.x);
            s4[i] = v;
        }
        __syncthreads();

        // P3: this group's contiguous slice of the chunk
        const int slice = (cnt + GROUPS - 1) / GROUPS;
        const int i0 = min(g * slice, cnt);
        const int i1 = min(i0 + slice, cnt);

        #pragma unroll 4
        for (int i = i0; i < i1; i++) {
            const float4 v = s4[i];
            const int p = base + i;
            {   // ego
                const float x = fmaf(v.x, qe.x, fmaf(v.y, qe.y, -v.z));
                const float y = fmaf(v.x, qe.y, -fmaf(v.y, qe.x, v.w));
                float d = fmaf(fabsf(y), 10.0f, fabsf(x));
                if (x > 0.0f) d += 1000.0f;
                if (d < beE) { beE = d; biE = p; }
            }
            {   // expert
                const float x = fmaf(v.x, qc.x, fmaf(v.y, qc.y, -v.z));
                const float y = fmaf(v.x, qc.y, -fmaf(v.y, qc.x, v.w));
                float d = fmaf(fabsf(y), 10.0f, fabsf(x));
                if (x > 0.0f) d += 1000.0f;
                if (d < beX) { beX = d; biX = p; }
            }
        }

        // winner recompute while chunk resident
        if (biE >= base) {
            const float4 v = s4[biE - base];
            bxE = fmaf(v.x, qe.x,  fmaf(v.y, qe.y,  -v.z));
            bpE = fmaf(v.x, qep.x, fmaf(v.y, qep.y, -v.z));
        }
        if (biX >= base) {
            const float4 v = s4[biX - base];
            bxX = fmaf(v.x, qc.x,  fmaf(v.y, qc.y,  -v.z));
            bpX = fmaf(v.x, qcp.x, fmaf(v.y, qcp.y, -v.z));
        }
        __syncthreads();
    }

    // P4a: block-internal combine (ascending g = ascending index)
    redD[0][g][t] = beE;
    redP[0][g][t] = (beE < CUDART_INF_F) ? (bxE - bpE) : 0.0f;
    redD[1][g][t] = beX;
    redP[1][g][t] = (beX < CUDART_INF_F) ? (bxX - bpX) : 0.0f;
    __syncthreads();

    if (tid < 64) {
        const int role = tid >> 5, tt = tid & 31;
        float cb = CUDART_INF_F, cp = 0.0f;
        #pragma unroll
        for (int gg = 0; gg < GROUPS; gg++) {
            const float d = redD[role][gg][tt];
            if (d < cb) { cb = d; cp = redP[role][gg][tt]; }
        }
        const int qo = (b * NSPLIT + s) * 64 + tid;
        g_pd[qo] = cb;
        g_pp[qo] = cp;
    }
    __threadfence();
    __syncthreads();

    if (tid == 0) {
        if (atomicAdd(&g_done[b], 1) == nsplit - 1) { __threadfence(); s_fin = 1; }
    }
    __syncthreads();

    if (s_fin) {   // P4b: last sibling combines partials (ascending s)
        if (tid < 64) {
            float cb = CUDART_INF_F, cp = 0.0f;
            for (int ss = 0; ss < nsplit; ss++) {
                const float d = g_pd[(b * NSPLIT + ss) * 64 + tid];
                if (d < cb) { cb = d; cp = g_pp[(b * NSPLIT + ss) * 64 + tid]; }
            }
            float prog = cp;
            #pragma unroll
            for (int o = 16; o > 0; o >>= 1)
                prog += __shfl_down_sync(0xFFFFFFFFu, prog, o);
            if ((tid & 31) == 0) s_sum[tid >> 5] = prog;
        }
        __syncthreads();
        if (tid == 0) {
            out[b] = fminf(fmaxf(s_sum[0], 2.0f) / fmaxf(s_sum[1], 2.0f), 1.0f);
            g_done[b] = 0;                         // restore for next replay
        }
    }

    // global epilogue: last block resets barrier counters (every block has
    // passed barrier 1 before any g_sync2 arrival -> no lost wakeups)
    if (tid == 0) {
        if (atomicAdd(&g_sync2, 1) == grid - 1) {
            g_sync1 = 0;
            g_sync2 = 0;
        }
    }
}

extern "C" void kernel_launch(void* const* d_in, const int* in_sizes, int n_in,
                              void* d_out, int out_size)
{
    const int*   poly_batch    = (const int*)  d_in[0];
    const float* poly_pos      = (const float*)d_in[1];
    const float* poly_heading  = (const float*)d_in[2];
    const int*   edge_index    = (const int*)  d_in[3];
    const int*   on_route_mask = (const int*)  d_in[4];
    const int*   agent_ptr     = (const int*)  d_in[5];
    const float* infer_pos     = (const float*)d_in[6];
    const int*   agent_batch   = (const int*)  d_in[7];
    const float* agent_pos     = (const float*)d_in[8];
    float*       out           = (float*)      d_out;

    const int P = in_sizes[0];
    int B       = in_sizes[5] - 1;
    if (B > B_MAX) B = B_MAX;

    // single-wave guarantee for the spin barrier: grid <= 148
    int nsplit = NSPLIT;
    while (nsplit > 1 && B * nsplit > 148) nsplit >>= 1;

    progress_reward_kernel<<<B * nsplit, TPB>>>(
        poly_batch, poly_pos, poly_heading, edge_index, on_route_mask,
        agent_ptr, infer_pos, agent_batch, agent_pos, out, P, B, nsplit);
}

// round 8
// speedup vs baseline: 1.0668x; 1.0668x over previous
#include <cuda_runtime.h>
#include <math_constants.h>

// ProgressReward — round 7: polyline-major decomposition + packed atomic argmin.
//
// Phase 1 (starts at cycle 0, no data-dependent routing):
//   Block i owns static polyline chunk [i*chunk, ...). Reads poly_batch of its
//   chunk to learn the spanned batches (1-2 here), prefetches those batches'
//   query points (agent_ptr[bb] -> positions; chain begins immediately via
//   poly_batch[c0]), stages candidates (c,s,a,bv float4; off-route => a=+INF),
//   evaluates 64 queries x candidates, and publishes per-(batch,query) minima
//   with atomicMax(g_win, ~packed), packed = (dist_bits<<32)|poly_index.
//   Unsigned-min of packed == (min dist, then min index) == jnp.argmin
//   first-min semantics, independent of evaluation order. Zero-init scratch
//   (complement trick) + post-consume reset => CUDA-graph replay safe.
// Grid spin barrier (grid<=148, single wave).
// Phase 2: block b (<B) reads its 64 winners (L2-hot), recomputes x/x_pre
//   from the winning polyline, reduces over 32 timesteps per role, writes
//   out[b] = min(max(pE,2)/max(pX,2), 1), resets its scratch words.
//
// ego batch id: agent_batch[agent_ptr[b]] == b (CSR invariant).

#define NUM_HIST 4
#define INTERVAL 5
#define IP_ROWS  36
#define L_ROWS   180
#define TPB      512
#define SUBCH    320     // max candidates staged at once
#define QS       8       // max batch slots prefetched at once
#define B_MAX    256

__device__ unsigned long long g_win[B_MAX * 64];   // zero-init; self-resetting
__device__ int g_sync1, g_sync2;                   // zero-init; self-resetting

__global__ void __launch_bounds__(TPB)
progress_reward_kernel(
    const int*   __restrict__ poly_batch,
    const float* __restrict__ poly_pos,        // (P,2)
    const float* __restrict__ poly_heading,    // (P,)
    const int*   __restrict__ edge_index,      // (2,P)
    const int*   __restrict__ on_route_mask,   // (NG,) int32 bool
    const int*   __restrict__ agent_ptr,       // (B+1,)
    const float* __restrict__ infer_pos,       // (A,36,2)
    const int*   __restrict__ agent_batch,     // (A,) (unused; CSR invariant)
    const float* __restrict__ agent_pos,       // (A,180,2)
    float*       __restrict__ out,             // (B,)
    int P, int B)
{
    __shared__ float4             s4[SUBCH];             // staged candidates
    __shared__ int                s_batch[SUBCH];
    __shared__ int                s_bnd[B_MAX + 2];
    __shared__ float4             s_q[QS][64];           // (curx,cury,prex,prey)
    __shared__ int                s_aidx[QS];
    __shared__ unsigned long long red64[8][64];
    __shared__ float              s_sum[2];

    const int grid = gridDim.x;
    const int bi   = blockIdx.x;
    const int tid  = threadIdx.x;
    const int g    = tid >> 6;          // 0..7 candidate-slice group
    const int sub  = tid & 63;          // query id within batch
    const int role = sub >> 5;          // 0=ego 1=expert
    const int t    = sub & 31;          // timestep

    const int chunk = (P + grid - 1) / grid;
    const int c0 = bi * chunk;
    const int c1 = min(c0 + chunk, P);

    // ---- phase-2 query prefetch (independent; chain starts at cycle 0) ----
    float2 p2c = make_float2(0.f, 0.f), p2p = make_float2(0.f, 0.f);
    if (bi < B && tid < 64) {
        const int aidx2 = agent_ptr[bi];
        if (role == 0) {
            const float2* ip = (const float2*)(infer_pos + (size_t)aidx2 * (IP_ROWS * 2));
            p2c = ip[NUM_HIST + t];
            p2p = ip[NUM_HIST - 1 + t];
        } else {
            const float2* ap = (const float2*)(agent_pos + (size_t)aidx2 * (L_ROWS * 2));
            p2c = ap[(4 + t) * INTERVAL];
            p2p = ap[(3 + t) * INTERVAL];
        }
    }

    const float2* pp2 = (const float2*)poly_pos;

    // ================= phase 1: scan my static polyline chunk =================
    if (c0 < c1) {
        for (int base = c0; base < c1; base += SUBCH) {
            const int cnt = min(SUBCH, c1 - base);

            // stage candidates
            for (int i = tid; i < cnt; i += TPB) {
                const int p = base + i;
                const int v = poly_batch[p];
                s_batch[i] = v;
                const float2 pos = pp2[p];
                const float h  = poly_heading[p];
                const float ch = cosf(h);
                const float sh = sinf(h);
                const int poly = edge_index[P + p];
                const int on   = on_route_mask[poly];
                float4 w;
                w.x = ch;
                w.y = sh;
                w.z = on ? fmaf(ch, pos.x, sh * pos.y) : CUDART_INF_F;
                w.w = fmaf(ch, pos.y, -sh * pos.x);
                s4[i] = w;
            }
            __syncthreads();

            const int sb0 = s_batch[0];
            const int sb1 = s_batch[cnt - 1];

            // batch boundaries within this sub-chunk
            for (int i = tid; i < cnt; i += TPB) {
                const int v = s_batch[i];
                if (i == 0) s_bnd[v] = 0;
                else {
                    const int vp = s_batch[i - 1];
                    for (int w = vp + 1; w <= v; w++) s_bnd[w] = i;
                }
            }
            if (tid == 0) s_bnd[sb1 + 1] = cnt;
            __syncthreads();

            // process spanned batches in groups of QS slots
            for (int bq = sb0; bq <= sb1; bq += QS) {
                const int nq = min(QS, sb1 - bq + 1);

                // prefetch queries for these batches
                if (tid < nq) s_aidx[tid] = agent_ptr[bq + tid];
                __syncthreads();
                if (tid < nq * 64) {
                    const int k  = tid >> 6;
                    const int qs = tid & 63;
                    const int qr = qs >> 5, qt = qs & 31;
                    const int ax = s_aidx[k];
                    float2 qc2, qp2;
                    if (qr == 0) {
                        const float2* ip = (const float2*)(infer_pos + (size_t)ax * (IP_ROWS * 2));
                        qc2 = ip[NUM_HIST + qt];
                        qp2 = ip[NUM_HIST - 1 + qt];
                    } else {
                        const float2* ap = (const float2*)(agent_pos + (size_t)ax * (L_ROWS * 2));
                        qc2 = ap[(4 + qt) * INTERVAL];
                        qp2 = ap[(3 + qt) * INTERVAL];
                    }
                    s_q[k][qs] = make_float4(qc2.x, qc2.y, qp2.x, qp2.y);
                }
                __syncthreads();

                for (int k = 0; k < nq; k++) {
                    const int bb = bq + k;
                    const int r0 = s_bnd[bb];
                    const int r1 = s_bnd[bb + 1];
                    const int m  = r1 - r0;

                    unsigned long long pk = ~0ULL;
                    if (m > 0) {
                        const float4 q = s_q[k][sub];
                        float best = CUDART_INF_F;
                        int   bix  = 0;
                        const int slice = (m + 7) >> 3;
                        const int i0 = r0 + g * slice;
                        const int i1 = min(i0 + slice, r1);
                        #pragma unroll 4
                        for (int i = i0; i < i1; i++) {
                            const float4 v = s4[i];
                            const float x = fmaf(v.x, q.x, fmaf(v.y, q.y, -v.z));
                            const float y = fmaf(v.x, q.y, -fmaf(v.y, q.x, v.w));
                            float d = fmaf(fabsf(y), 10.0f, fabsf(x));
                            if (x > 0.0f) d += 1000.0f;
                            if (d < best) { best = d; bix = base + i; }
                        }
                        if (best < CUDART_INF_F)
                            pk = ((unsigned long long)__float_as_uint(best) << 32)
                                 | (unsigned)bix;
                    }
                    red64[g][sub] = pk;
                    __syncthreads();

                    if (tid < 64) {
                        unsigned long long mn = red64[0][tid];
                        #pragma unroll
                        for (int gg = 1; gg < 8; gg++) {
                            const unsigned long long v = red64[gg][tid];
                            if (v < mn) mn = v;
                        }
                        if (mn != ~0ULL)
                            atomicMax(&g_win[bb * 64 + tid], ~mn);
                    }
                    __syncthreads();
                }
            }
            __syncthreads();
        }
    }

    // ======================= grid barrier =======================
    __threadfence();
    if (tid == 0) {
        atomicAdd(&g_sync1, 1);
        while (*(volatile int*)&g_sync1 < grid) { }
    }
    __syncthreads();
    __threadfence();

    // ============ phase 2: block b finishes batch b (L2-hot) ============
    if (bi < B && tid < 64) {
        const unsigned long long w = ~g_win[bi * 64 + tid];
        g_win[bi * 64 + tid] = 0;                     // reset for next replay
        float prog = 0.0f;
        const unsigned dbits = (unsigned)(w >> 32);
        if (dbits < 0x7F800000u) {                    // finite best dist
            const int idx = (int)(unsigned)w;
            const float2 pos = pp2[idx];
            const float h  = poly_heading[idx];
            const float ch = cosf(h);
            const float sh = sinf(h);
            const float a  = fmaf(ch, pos.x, sh * pos.y);
            const float x  = fmaf(ch, p2c.x, fmaf(sh, p2c.y, -a));
            const float xp = fmaf(ch, p2p.x, fmaf(sh, p2p.y, -a));
            prog = x - xp;
        }
        #pragma unroll
        for (int o = 16; o > 0; o >>= 1)
            prog += __shfl_down_sync(0xFFFFFFFFu, prog, o);
        if (t == 0) s_sum[role] = prog;
    }
    __syncthreads();
    if (bi < B && tid == 0)
        out[bi] = fminf(fmaxf(s_sum[0], 2.0f) / fmaxf(s_sum[1], 2.0f), 1.0f);

    // epilogue: last block resets barrier counters
    if (tid == 0) {
        if (atomicAdd(&g_sync2, 1) == grid - 1) {
            g_sync1 = 0;
            g_sync2 = 0;
        }
    }
}

extern "C" void kernel_launch(void* const* d_in, const int* in_sizes, int n_in,
                              void* d_out, int out_size)
{
    const int*   poly_batch    = (const int*)  d_in[0];
    const float* poly_pos      = (const float*)d_in[1];
    const float* poly_heading  = (const float*)d_in[2];
    const int*   edge_index    = (const int*)  d_in[3];
    const int*   on_route_mask = (const int*)  d_in[4];
    const int*   agent_ptr     = (const int*)  d_in[5];
    const float* infer_pos     = (const float*)d_in[6];
    const int*   agent_batch   = (const int*)  d_in[7];
    const float* agent_pos     = (const float*)d_in[8];
    float*       out           = (float*)      d_out;

    const int P = in_sizes[0];
    int B       = in_sizes[5] - 1;
    if (B > B_MAX) B = B_MAX;

    int grid = 128;                       // single wave (<=148) for spin barrier
    if (B > grid) grid = (B <= 148) ? B : 148;

    progress_reward_kernel<<<grid, TPB>>>(
        poly_batch, poly_pos, poly_heading, edge_index, on_route_mask,
        agent_ptr, infer_pos, agent_batch, agent_pos, out, P, B);
}

// round 9
// speedup vs baseline: 1.1910x; 1.1164x over previous
#include <cuda_runtime.h>
#include <math_constants.h>

// ProgressReward — round 8: polyline-major, single-sync phase-1 pipeline.
//
// Block i owns static polyline chunk [i*chunk, i*chunk+cnt). Phase 1 has ONE
// __syncthreads before eval:
//   warp 15 (producer): pb[ends] -> spanned batches [sb0,sb1] -> agent_ptr ->
//     query points into s_q (3 chained RTs, starts cycle 0)
//   warps 0-14 (stage): per-candidate pb[p], pb[p-1], pos, heading, edge ->
//     mask; writes float4 (c,s,a|+INF,bv) AND batch boundaries s_bnd directly
//     (2 chained RTs, overlapping the producer)
// Eval: 8 groups x 64 queries scan candidate slices; each thread publishes
// its slice-best per (batch,query) with atomicMax(g_win, ~packed),
// packed=(dist_bits<<32)|poly_idx  => unsigned min == (min dist, min index)
// == jnp.argmin first-min, order-independent (no intra-block reduce needed).
// Grid spin barrier (single wave, grid<=148). Phase 2: block b<B reads its 64
// winners (L2-hot), recomputes x/x_pre, reduces, writes out[b], resets its
// g_win words. Zero-init + complement packing + resets => graph-replay safe.

#define NUM_HIST 4
#define INTERVAL 5
#define IP_ROWS  36
#define L_ROWS   180
#define TPB      512
#define SUBCH    512
#define QS       8
#define B_MAX    256

__device__ unsigned long long g_win[B_MAX * 64];   // zero-init; self-resetting
__device__ int g_sync1, g_sync2;                   // zero-init; self-resetting

__global__ void __launch_bounds__(TPB)
progress_reward_kernel(
    const int*   __restrict__ poly_batch,
    const float* __restrict__ poly_pos,        // (P,2)
    const float* __restrict__ poly_heading,    // (P,)
    const int*   __restrict__ edge_index,      // (2,P)
    const int*   __restrict__ on_route_mask,   // (NG,) int32 bool
    const int*   __restrict__ agent_ptr,       // (B+1,)
    const float* __restrict__ infer_pos,       // (A,36,2)
    const int*   __restrict__ agent_batch,     // (A,) unused (CSR invariant)
    const float* __restrict__ agent_pos,       // (A,180,2)
    float*       __restrict__ out,             // (B,)
    int P, int B)
{
    __shared__ float4 s4[SUBCH];               // candidates (c,s,a,bv)
    __shared__ int    s_bnd[B_MAX + 2];
    __shared__ float4 s_q[QS][64];             // (curx,cury,prex,prey)
    __shared__ int    s_b0, s_b1;
    __shared__ int    s_aidx[QS];              // fallback path only
    __shared__ float  s_sum[2];

    const int grid = gridDim.x;
    const int bi   = blockIdx.x;
    const int tid  = threadIdx.x;
    const int lane = tid & 31;
    const int warp = tid >> 5;
    const int g    = tid >> 6;                 // 0..7 candidate-slice group
    const int sub  = tid & 63;                 // query id
    const int role = sub >> 5;
    const int t    = sub & 31;

    const int chunk = (P + grid - 1) / grid;
    const int c0 = bi * chunk;
    const int c1 = min(c0 + chunk, P);

    // ---- phase-2 query prefetch (independent, cycle 0) ----
    float2 p2c = make_float2(0.f, 0.f), p2p = make_float2(0.f, 0.f);
    if (bi < B && tid < 64) {
        const int a2 = agent_ptr[bi];
        if (role == 0) {
            const float2* ip = (const float2*)(infer_pos + (size_t)a2 * (IP_ROWS * 2));
            p2c = ip[NUM_HIST + t];
            p2p = ip[NUM_HIST - 1 + t];
        } else {
            const float2* ap = (const float2*)(agent_pos + (size_t)a2 * (L_ROWS * 2));
            p2c = ap[(4 + t) * INTERVAL];
            p2p = ap[(3 + t) * INTERVAL];
        }
    }

    const float2* pp2 = (const float2*)poly_pos;

    // ================= phase 1 =================
    for (int base = c0; base < c1; base += SUBCH) {
        const int cnt = min(SUBCH, c1 - base);

        if (warp == 15) {
            // ---- producer: batch span + query staging ----
            int e = 0;
            if (lane == 0) e = poly_batch[base];
            if (lane == 1) e = poly_batch[base + cnt - 1];
            const int sb0 = __shfl_sync(0xFFFFFFFFu, e, 0);
            const int sb1 = __shfl_sync(0xFFFFFFFFu, e, 1);
            if (lane == 0) { s_b0 = sb0; s_b1 = sb1; }
            if (lane == 2) s_bnd[sb1 + 1] = cnt;
            const int nq = min(sb1 - sb0 + 1, QS);
            int ax = 0;
            if (lane < nq) ax = agent_ptr[sb0 + lane];
            for (int k = 0; k < nq; k++) {
                const int a = __shfl_sync(0xFFFFFFFFu, ax, k);
                const float2* ip = (const float2*)(infer_pos + (size_t)a * (IP_ROWS * 2));
                float2 qc2 = ip[NUM_HIST + lane];
                float2 qp2 = ip[NUM_HIST - 1 + lane];
                s_q[k][lane] = make_float4(qc2.x, qc2.y, qp2.x, qp2.y);
                const float2* ap = (const float2*)(agent_pos + (size_t)a * (L_ROWS * 2));
                qc2 = ap[(4 + lane) * INTERVAL];
                qp2 = ap[(3 + lane) * INTERVAL];
                s_q[k][32 + lane] = make_float4(qc2.x, qc2.y, qp2.x, qp2.y);
            }
        } else {
            // ---- stage: candidates + boundaries, no smem dependencies ----
            for (int i = tid; i < cnt; i += (TPB - 32)) {
                const int p  = base + i;
                const int v  = poly_batch[p];
                const int vp = (i > 0) ? poly_batch[p - 1] : v;  // i==0 handled below
                const float2 pos = pp2[p];
                const float h  = poly_heading[p];
                const int poly = edge_index[P + p];
                const float ch = cosf(h);
                const float sh = sinf(h);
                const int on   = on_route_mask[poly];
                float4 w;
                w.x = ch;
                w.y = sh;
                w.z = on ? fmaf(ch, pos.x, sh * pos.y) : CUDART_INF_F;
                w.w = fmaf(ch, pos.y, -sh * pos.x);
                s4[i] = w;
                if (i == 0) s_bnd[v] = 0;
                else
                    for (int b2 = vp + 1; b2 <= v; b2++) s_bnd[b2] = i;
            }
        }
        __syncthreads();

        const int sb0 = s_b0;
        const int sb1 = s_b1;

        for (int bq = sb0; bq <= sb1; bq += QS) {
            const int nqw = min(QS, sb1 - bq + 1);

            if (bq != sb0) {
                // rare fallback: restage queries for span > QS batches
                __syncthreads();
                if (tid < nqw) s_aidx[tid] = agent_ptr[bq + tid];
                __syncthreads();
                if (tid < nqw * 64) {
                    const int k  = tid >> 6;
                    const int qs = tid & 63;
                    const int qr = qs >> 5, qt = qs & 31;
                    const int a  = s_aidx[k];
                    float2 qc2, qp2;
                    if (qr == 0) {
                        const float2* ip = (const float2*)(infer_pos + (size_t)a * (IP_ROWS * 2));
                        qc2 = ip[NUM_HIST + qt];
                        qp2 = ip[NUM_HIST - 1 + qt];
                    } else {
                        const float2* ap = (const float2*)(agent_pos + (size_t)a * (L_ROWS * 2));
                        qc2 = ap[(4 + qt) * INTERVAL];
                        qp2 = ap[(3 + qt) * INTERVAL];
                    }
                    s_q[k][qs] = make_float4(qc2.x, qc2.y, qp2.x, qp2.y);
                }
                __syncthreads();
            }

            for (int k = 0; k < nqw; k++) {
                const int bb = bq + k;
                const int r0 = s_bnd[bb];
                const int r1 = s_bnd[bb + 1];
                const int m  = r1 - r0;
                if (m <= 0) continue;

                const float4 q = s_q[k][sub];
                float best = CUDART_INF_F;
                int   bix  = 0;
                const int slice = (m + 7) >> 3;
                const int i0 = r0 + g * slice;
                const int i1 = min(i0 + slice, r1);
                #pragma unroll 4
                for (int i = i0; i < i1; i++) {
                    const float4 v = s4[i];
                    const float x = fmaf(v.x, q.x, fmaf(v.y, q.y, -v.z));
                    const float y = fmaf(v.x, q.y, -fmaf(v.y, q.x, v.w));
                    float d = fmaf(fabsf(y), 10.0f, fabsf(x));
                    if (x > 0.0f) d += 1000.0f;
                    if (d < best) { best = d; bix = base + i; }
                }
                if (best < CUDART_INF_F) {
                    const unsigned long long pk =
                        ((unsigned long long)__float_as_uint(best) << 32)
                        | (unsigned)bix;
                    atomicMax(&g_win[bb * 64 + sub], ~pk);
                }
            }
        }
        __syncthreads();    // smem reuse across sub-chunks
    }

    // ================= grid barrier =================
    __threadfence();
    if (tid == 0) {
        atomicAdd(&g_sync1, 1);
        while (*(volatile int*)&g_sync1 < grid) { }
    }
    __syncthreads();
    __threadfence();

    // ================= phase 2 =================
    if (bi < B && tid < 64) {
        const unsigned long long w = ~g_win[bi * 64 + tid];
        g_win[bi * 64 + tid] = 0;                  // reset for next replay
        float prog = 0.0f;
        const unsigned dbits = (unsigned)(w >> 32);
        if (dbits < 0x7F800000u) {                 // finite best dist
            const int idx = (int)(unsigned)w;
            const float2 pos = pp2[idx];
            const float h  = poly_heading[idx];
            const float ch = cosf(h);
            const float sh = sinf(h);
            const float a  = fmaf(ch, pos.x, sh * pos.y);
            const float x  = fmaf(ch, p2c.x, fmaf(sh, p2c.y, -a));
            const float xp = fmaf(ch, p2p.x, fmaf(sh, p2p.y, -a));
            prog = x - xp;
        }
        #pragma unroll
        for (int o = 16; o > 0; o >>= 1)
            prog += __shfl_down_sync(0xFFFFFFFFu, prog, o);
        if (t == 0) s_sum[role] = prog;
    }
    __syncthreads();
    if (bi < B && tid == 0)
        out[bi] = fminf(fmaxf(s_sum[0], 2.0f) / fmaxf(s_sum[1], 2.0f), 1.0f);

    // last block resets barrier counters (all blocks already past barrier 1)
    if (tid == 0) {
        if (atomicAdd(&g_sync2, 1) == grid - 1) {
            g_sync1 = 0;
            g_sync2 = 0;
        }
    }
}

extern "C" void kernel_launch(void* const* d_in, const int* in_sizes, int n_in,
                              void* d_out, int out_size)
{
    const int*   poly_batch    = (const int*)  d_in[0];
    const float* poly_pos      = (const float*)d_in[1];
    const float* poly_heading  = (const float*)d_in[2];
    const int*   edge_index    = (const int*)  d_in[3];
    const int*   on_route_mask = (const int*)  d_in[4];
    const int*   agent_ptr     = (const int*)  d_in[5];
    const float* infer_pos     = (const float*)d_in[6];
    const int*   agent_batch   = (const int*)  d_in[7];
    const float* agent_pos     = (const float*)d_in[8];
    float*       out           = (float*)      d_out;

    const int P = in_sizes[0];
    int B       = in_sizes[5] - 1;
    if (B > B_MAX) B = B_MAX;

    int grid = 128;                            // single wave for spin barrier
    if (B > grid) grid = (B <= 148) ? B : 148;

    progress_reward_kernel<<<grid, TPB>>>(
        poly_batch, poly_pos, poly_heading, edge_index, on_route_mask,
        agent_ptr, infer_pos, agent_batch, agent_pos, out, P, B);
}